// round 1
// baseline (speedup 1.0000x reference)
#include <cuda_runtime.h>
#include <cuda_bf16.h>
#include <cstdint>

// Hardware tanh (MUFU.TANH, sm_75+). Lat ~16 cyc, single instruction.
__device__ __forceinline__ float htanh(float x) {
    float y;
    asm("tanh.approx.f32 %0, %1;" : "=f"(y) : "f"(x));
    return y;
}

// Scalar LSTM recurrence, output bit fed back as input.
// Key identities:
//   x_t == h_t  =>  z = h*(Wi+Wh) + b
//   sigmoid(z)  == 0.5*tanh(0.5*z) + 0.5   (fold the 0.5 into weights/bias)
// Fixed-point escape: once (c,h) repeats bitwise, all remaining outputs are
// identical; thread 0 breaks out and the whole block broadcast-fills the tail.
__global__ void __launch_bounds__(256, 1)
bitpredictor_lstm_kernel(const float* __restrict__ Wi,
                         const float* __restrict__ Wh,
                         const float* __restrict__ b,
                         float* __restrict__ out,
                         int n) {
    __shared__ float s_hfinal;
    __shared__ int   s_tstop;

    if (threadIdx.x == 0) {
        // Combined weights (x == h path)
        const float w0 = Wi[0] + Wh[0];
        const float w1 = Wi[1] + Wh[1];
        const float w2 = Wi[2] + Wh[2];
        const float w3 = Wi[3] + Wh[3];
        const float b0 = b[0], b1 = b[1], b2 = b[2], b3 = b[3];

        // Pre-scale sigmoid gates: sigmoid(h*w+b) = 0.5*tanh(h*(w/2)+(b/2)) + 0.5
        const float hw0 = 0.5f * w0, hb0 = 0.5f * b0;   // i gate
        const float hw1 = 0.5f * w1, hb1 = 0.5f * b1;   // f gate
        const float hw3 = 0.5f * w3, hb3 = 0.5f * b3;   // o gate

        float c = 0.0f, h = 0.0f;
        int tstop = n;
        float hfinal = 0.0f;

        #pragma unroll 1
        for (int t = 0; t < n; ++t) {
            // Gate pre-activations (4 independent FMAs, then 4 parallel MUFU.TANH)
            float ti = htanh(fmaf(h, hw0, hb0));
            float tf = htanh(fmaf(h, hw1, hb1));
            float g  = htanh(fmaf(h, w2,  b2));
            float to = htanh(fmaf(h, hw3, hb3));

            float gi = fmaf(0.5f, ti, 0.5f);
            float gf = fmaf(0.5f, tf, 0.5f);
            float go = fmaf(0.5f, to, 0.5f);

            float nc = fmaf(gf, c, gi * g);
            float nh = go * htanh(nc);

            out[t] = nh;

            if (nc == c && nh == h) {
                // Exact bitwise fixed point: all remaining outputs equal nh.
                tstop  = t + 1;
                hfinal = nh;
                break;
            }
            c = nc;
            h = nh;
        }
        s_tstop  = tstop;
        s_hfinal = hfinal;
    }
    __syncthreads();

    // Parallel broadcast-fill of the converged tail (no-op if no fixed point).
    const int   tstop  = s_tstop;
    const float hfinal = s_hfinal;
    for (int j = tstop + threadIdx.x; j < n; j += blockDim.x) {
        out[j] = hfinal;
    }
}

extern "C" void kernel_launch(void* const* d_in, const int* in_sizes, int n_in,
                              void* d_out, int out_size) {
    const float* Wi = (const float*)d_in[0];   // (1,4)
    const float* Wh = (const float*)d_in[1];   // (1,4)
    const float* b  = (const float*)d_in[2];   // (4,)
    float* out = (float*)d_out;                // (features,)
    bitpredictor_lstm_kernel<<<1, 256>>>(Wi, Wh, b, out, out_size);
}

// round 4
// speedup vs baseline: 1.3188x; 1.3188x over previous
#include <cuda_runtime.h>
#include <cuda_bf16.h>
#include <cstdint>

// Hardware tanh (MUFU.TANH, lat ~16 cyc).
__device__ __forceinline__ float htanh(float x) {
    float y;
    asm("tanh.approx.f32 %0, %1;" : "=f"(y) : "f"(x));
    return y;
}

// Scalar LSTM recurrence; output fed back as input (x_t == h_t), so
//   z = h*(Wi+Wh) + b,    sigmoid(z) = 0.5*tanh(0.5*z) + 0.5.
//
// Chain restructure: keep state as (c, th, wgo_k) with h = go*th implicit.
// The w_k*go products are computed in the latency shadow of tanh(nc), so the
// steady-state critical path is:
//   fma(th,wgo,b)[4] -> tanh[16] -> gate affine[4] -> mul[4] -> fma nc[4]
//   -> tanh(nc)[16]  = 48 cycles/iter  (structural floor: two MUFU traversals
//   + 3 FFMA levels + front fma are irreducibly serial).
//
// Early exit: relative-tolerance fixed-point detection (2e-6; superset of
// bitwise equality). Converged tail is broadcast-filled by the block.
__global__ void __launch_bounds__(256, 1)
bitpredictor_lstm_kernel(const float* __restrict__ Wi,
                         const float* __restrict__ Wh,
                         const float* __restrict__ b,
                         float* __restrict__ out,
                         int n) {
    __shared__ float s_hfinal;
    __shared__ int   s_tstop;

    if (threadIdx.x == 0) {
        // Combined weights (x == h path)
        const float w0 = Wi[0] + Wh[0];
        const float w1 = Wi[1] + Wh[1];
        const float w2 = Wi[2] + Wh[2];
        const float w3 = Wi[3] + Wh[3];
        // sigmoid gates pre-scaled by 0.5 (i, f, o); g gate (tanh) unscaled.
        const float hw0 = 0.5f * w0, hb0 = 0.5f * b[0];
        const float hw1 = 0.5f * w1, hb1 = 0.5f * b[1];
        const float w2f = w2,        b2f = b[2];
        const float hw3 = 0.5f * w3, hb3 = 0.5f * b[3];

        // State: c, th (= tanh(c)), wgo_k = gate_weight * go_prev, h_prev.
        // Initial h = 0: th = 0, go irrelevant => wgo_k = weights.
        float c = 0.0f, th = 0.0f, h_prev = 0.0f;
        float wgo0 = hw0, wgo1 = hw1, wgo2 = w2f, wgo3 = hw3;

        int   tstop  = n;
        float hfinal = 0.0f;

        #pragma unroll 1
        for (int t = 0; t < n; ++t) {
            // Gate pre-activations: a_k = h*w_k + b_k = th*(w_k*go) + b_k
            float a0 = fmaf(th, wgo0, hb0);
            float a1 = fmaf(th, wgo1, hb1);
            float a2 = fmaf(th, wgo2, b2f);
            float a3 = fmaf(th, wgo3, hb3);

            float ti = htanh(a0);
            float tf = htanh(a1);
            float g  = htanh(a2);
            float to = htanh(a3);

            float gi = fmaf(0.5f, ti, 0.5f);
            float gf = fmaf(0.5f, tf, 0.5f);
            float go = fmaf(0.5f, to, 0.5f);

            float nc  = fmaf(gf, c, gi * g);
            float nth = htanh(nc);          // 16-cyc shadow hides the work below

            // Off-critical-path: next iteration's fused weights and output.
            float nwgo0 = hw0 * go;
            float nwgo1 = hw1 * go;
            float nwgo2 = w2f * go;
            float nwgo3 = hw3 * go;
            float nh    = go * nth;

            out[t] = nh;

            // Fixed-point detection (relative tolerance).
            bool conv = (fabsf(nh - h_prev) <= fmaf(2e-6f, fabsf(nh), 1e-12f)) &
                        (fabsf(nc - c)      <= fmaf(2e-6f, fabsf(nc), 1e-12f));
            if (conv) {
                tstop  = t + 1;
                hfinal = nh;
                break;
            }

            c = nc; th = nth; h_prev = nh;
            wgo0 = nwgo0; wgo1 = nwgo1; wgo2 = nwgo2; wgo3 = nwgo3;
        }
        s_tstop  = tstop;
        s_hfinal = hfinal;
    }
    __syncthreads();

    // Parallel broadcast-fill of the converged tail.
    const int   tstop  = s_tstop;
    const float hfinal = s_hfinal;
    for (int j = tstop + threadIdx.x; j < n; j += blockDim.x) {
        out[j] = hfinal;
    }
}

extern "C" void kernel_launch(void* const* d_in, const int* in_sizes, int n_in,
                              void* d_out, int out_size) {
    const float* Wi = (const float*)d_in[0];   // (1,4)
    const float* Wh = (const float*)d_in[1];   // (1,4)
    const float* b  = (const float*)d_in[2];   // (4,)
    float* out = (float*)d_out;                // (features,)
    bitpredictor_lstm_kernel<<<1, 256>>>(Wi, Wh, b, out, out_size);
}